// round 7
// baseline (speedup 1.0000x reference)
#include <cuda_runtime.h>
#include <math.h>
#include <stdint.h>

typedef unsigned long long ull;
typedef unsigned short u16;

#define NN 4096
#define UN 256
#define BT 512

// ================= helpers =================
__device__ __forceinline__ ull pack2(float x, float y){
    ull r; asm("mov.b64 %0, {%1, %2};" : "=l"(r) : "f"(x), "f"(y)); return r;
}
__device__ __forceinline__ void fma2(ull& d, ull a, ull b){
    asm("fma.rn.f32x2 %0, %1, %2, %3;" : "=l"(d) : "l"(a), "l"(b), "l"(d));
}
__device__ __forceinline__ float2 unpack2(ull v){
    float lo, hi; asm("mov.b64 {%0, %1}, %2;" : "=f"(lo), "=f"(hi) : "l"(v));
    return make_float2(lo, hi);
}
__device__ __forceinline__ uint32_t smem_u32(const void* p){
    uint32_t a;
    asm("{ .reg .u64 t; cvta.to.shared.u64 t, %1; cvt.u32.u64 %0, t; }" : "=r"(a) : "l"(p));
    return a;
}
__device__ __forceinline__ void cpasync16(uint32_t daddr, const void* gptr){
    asm volatile("cp.async.cg.shared.global [%0], [%1], 16;" :: "r"(daddr), "l"(gptr));
}
#define CP_COMMIT asm volatile("cp.async.commit_group;" ::: "memory")
#define CP_WAIT0  asm volatile("cp.async.wait_group 0;" ::: "memory")

// fp16 hi/lo split helpers (identical numerics to R5)
__device__ __forceinline__ void split2h(float v0, float v1, uint32_t& hp, uint32_t& lp){
    u16 h0, h1, l0, l1;
    asm("cvt.rn.f16.f32 %0, %1;" : "=h"(h0) : "f"(v0));
    asm("cvt.rn.f16.f32 %0, %1;" : "=h"(h1) : "f"(v1));
    float f0, f1;
    asm("cvt.f32.f16 %0, %1;" : "=f"(f0) : "h"(h0));
    asm("cvt.f32.f16 %0, %1;" : "=f"(f1) : "h"(h1));
    asm("cvt.rn.f16.f32 %0, %1;" : "=h"(l0) : "f"(v0 - f0));
    asm("cvt.rn.f16.f32 %0, %1;" : "=h"(l1) : "f"(v1 - f1));
    asm("mov.b32 %0, {%1, %2};" : "=r"(hp) : "h"(h0), "h"(h1));
    asm("mov.b32 %0, {%1, %2};" : "=r"(lp) : "h"(l0), "h"(l1));
}
__device__ __forceinline__ void split1h(float v, u16& h, u16& l){
    u16 hb, lb;
    asm("cvt.rn.f16.f32 %0, %1;" : "=h"(hb) : "f"(v));
    float hf;
    asm("cvt.f32.f16 %0, %1;" : "=f"(hf) : "h"(hb));
    asm("cvt.rn.f16.f32 %0, %1;" : "=h"(lb) : "f"(v - hf));
    h = hb; l = lb;
}
__device__ __forceinline__ u16 cvt1h(float v){
    u16 hb;
    asm("cvt.rn.f16.f32 %0, %1;" : "=h"(hb) : "f"(v));
    return hb;
}

__device__ __forceinline__ void mma16816h(float* d, const uint32_t* a, const uint32_t* b){
    asm volatile("mma.sync.aligned.m16n8k16.row.col.f32.f16.f16.f32 "
        "{%0,%1,%2,%3}, {%4,%5,%6,%7}, {%8,%9}, {%0,%1,%2,%3};"
        : "+f"(d[0]), "+f"(d[1]), "+f"(d[2]), "+f"(d[3])
        : "r"(a[0]), "r"(a[1]), "r"(a[2]), "r"(a[3]), "r"(b[0]), "r"(b[1]));
}

// ================= static device scratch =================
__device__ __align__(16) float g_partialG[4u * NN * UN];   // 16 MB
__device__ __align__(16) u16   g_wth[UN * NN];             // 2 MB  w_gcn^T fp16
__device__ __align__(16) u16   g_Gt_hi[UN * NN];           // 2 MB  G^T fp16 hi
__device__ __align__(16) u16   g_Gt_lo[UN * NN];           // 2 MB
__device__ __align__(16) float g_partialX[8u * BT * UN];   // 4 MB
__device__ __align__(16) float g_X[BT * UN];               // 0.5 MB

// ================= SMEM geometry =================
#define ROWB 80
// kernelA: [A_hi 2560][A_lo 2560][B 20480]  (M=32, N=256, BK=32)
#define A_OFF_AHI 0
#define A_OFF_ALO 2560
#define A_OFF_B   5120
#define A_BUFST   25600
#define A_SMEMSZ  (2 * A_BUFST)
// kernelB: [A_hi 2560][A_lo 2560][B_hi 10240][B_lo 10240]  (M=32, N=128, BK=32)
#define B_OFF_AHI 0
#define B_OFF_ALO 2560
#define B_OFF_BHI 5120
#define B_OFF_BLO 15360
#define B_BUFST   25600
#define B_SMEMSZ  (2 * B_BUFST)

// =====================================================================
// kPrepW: w_gcn [4096][256] -> g_wth [256][4096] fp16 (transpose)
// =====================================================================
__global__ void kPrepW(const float* __restrict__ wgcn)
{
    __shared__ float tile[32][33];
    const int k0 = blockIdx.x * 32, n0 = blockIdx.y * 32;
    const int c = threadIdx.x & 31, r = threadIdx.x >> 5;
#pragma unroll
    for (int i = 0; i < 4; i++)
        tile[r + 8*i][c] = wgcn[(size_t)(k0 + r + 8*i) * UN + n0 + c];
    __syncthreads();
#pragma unroll
    for (int i = 0; i < 4; i++){
        size_t o = (size_t)(n0 + r + 8*i) * NN + k0 + c;
        g_wth[o] = cvt1h(tile[c][r + 8*i]);
    }
}

// =====================================================================
// kernelA: partialG[ks] = adj_mix[m0:m0+32, ks*1024:+1024] @ w_gcn  (fp16 2-term)
// grid (128 m-tiles, 4 ksplit) = 512 CTAs, 256 threads, occ 2
// Per warp: M16 x N64 (8 warps as 2m x 4n). adj read exactly once chip-wide.
// =====================================================================
#define KA_NST 32     // 1024 / 32

__global__ __launch_bounds__(256, 2) void kernelA(const float* __restrict__ adj,
                                                  const float* __restrict__ wap)
{
    extern __shared__ __align__(16) char smem[];
    const uint32_t sb = smem_u32(smem);
    const int tid = threadIdx.x, wid = tid >> 5, lane = tid & 31;
    const int g = lane >> 2, tig = lane & 3;
    const int m0 = blockIdx.x * 32;
    const int kbase = blockIdx.y * 1024;
    const float w0 = wap[0], w1 = wap[1], w2 = wap[2];
    const size_t GS = (size_t)NN * NN;

    const int arow = tid >> 3;          // 0..31
    const int aq   = tid & 7;           // float4 col

    float acc[8][4];
#pragma unroll
    for (int b = 0; b < 8; b++)
#pragma unroll
        for (int c = 0; c < 4; c++) acc[b][c] = 0.f;

    float4 ra[3];

    auto issueB = [&](int t, int b){
#pragma unroll
        for (int j = 0; j < 4; j++){
            int f = j*256 + tid, row = f >> 2, c = f & 3;
            uint32_t daddr = sb + b*A_BUFST + A_OFF_B + row*ROWB + c*16;
            size_t go = (size_t)row * NN + kbase + t*32 + c*8;
            cpasync16(daddr, g_wth + go);
        }
        CP_COMMIT;
    };
    auto loadA = [&](int t){
        const float* p = adj + (size_t)(m0 + arow) * NN + kbase + t*32 + aq*4;
        ra[0] = __ldg((const float4*)p);
        ra[1] = __ldg((const float4*)(p + GS));
        ra[2] = __ldg((const float4*)(p + 2*GS));
    };
    auto storeA = [&](int b){
        char* base = smem + b*A_BUFST;
        float vx = fmaf(w0, ra[0].x, fmaf(w1, ra[1].x, w2*ra[2].x));
        float vy = fmaf(w0, ra[0].y, fmaf(w1, ra[1].y, w2*ra[2].y));
        float vz = fmaf(w0, ra[0].z, fmaf(w1, ra[1].z, w2*ra[2].z));
        float vw = fmaf(w0, ra[0].w, fmaf(w1, ra[1].w, w2*ra[2].w));
        uint32_t h0, l0, h1, l1;
        split2h(vx, vy, h0, l0);
        split2h(vz, vw, h1, l1);
        *(uint2*)(base + A_OFF_AHI + arow*ROWB + aq*8) = make_uint2(h0, h1);
        *(uint2*)(base + A_OFF_ALO + arow*ROWB + aq*8) = make_uint2(l0, l1);
    };

    issueB(0, 0);
    loadA(0); storeA(0);
    CP_WAIT0; __syncthreads();

    const int am = (wid & 1) * 16 + g;
    const int bn = (wid >> 1) * 64 + g;

    for (int t = 0; t < KA_NST; t++){
        const int b = t & 1;
        if (t + 1 < KA_NST){ issueB(t + 1, b ^ 1); loadA(t + 1); }

        const char* buf = smem + b*A_BUFST;
#pragma unroll
        for (int s = 0; s < 2; s++){
            const int ko = s * 32 + tig * 4;
            const char* pa = buf + A_OFF_AHI + am * ROWB + ko;
            uint32_t ah[4] = { *(const uint32_t*)pa,        *(const uint32_t*)(pa + 8*ROWB),
                               *(const uint32_t*)(pa + 16), *(const uint32_t*)(pa + 8*ROWB + 16) };
            const char* ql = buf + A_OFF_ALO + am * ROWB + ko;
            uint32_t al[4] = { *(const uint32_t*)ql,        *(const uint32_t*)(ql + 8*ROWB),
                               *(const uint32_t*)(ql + 16), *(const uint32_t*)(ql + 8*ROWB + 16) };
#pragma unroll
            for (int ni = 0; ni < 8; ni++){
                const char* pb = buf + A_OFF_B + (bn + ni*8) * ROWB + ko;
                uint32_t bh[2] = { *(const uint32_t*)pb, *(const uint32_t*)(pb + 16) };
                mma16816h(acc[ni], ah, bh);
                mma16816h(acc[ni], al, bh);
            }
        }

        if (t + 1 < KA_NST) storeA(b ^ 1);
        CP_WAIT0; __syncthreads();
    }

    float* dst = g_partialG + (size_t)blockIdx.y * (NN * UN);
    const int m = m0 + am;
#pragma unroll
    for (int ni = 0; ni < 8; ni++){
        int n = bn - g + ni*8 + tig*2;
        *(float2*)(dst + (size_t)m * UN + n)       = make_float2(acc[ni][0], acc[ni][1]);
        *(float2*)(dst + (size_t)(m + 8) * UN + n) = make_float2(acc[ni][2], acc[ni][3]);
    }
}

// =====================================================================
// kReduceGT: G = sum of 4 partials; transpose + fp16 split -> g_Gt_hi/lo
// =====================================================================
__global__ void kReduceGT()
{
    __shared__ float tile[32][33];
    const int k0 = blockIdx.x * 32, n0 = blockIdx.y * 32;
    const int c = threadIdx.x & 31, r = threadIdx.x >> 5;
#pragma unroll
    for (int i = 0; i < 4; i++){
        size_t o = (size_t)(k0 + r + 8*i) * UN + n0 + c;
        float s = g_partialG[o];
#pragma unroll
        for (int p = 1; p < 4; p++) s += g_partialG[(size_t)p * NN * UN + o];
        tile[r + 8*i][c] = s;
    }
    __syncthreads();
#pragma unroll
    for (int i = 0; i < 4; i++){
        float v = tile[c][r + 8*i];
        size_t o = (size_t)(n0 + r + 8*i) * NN + k0 + c;
        split1h(v, g_Gt_hi[o], g_Gt_lo[o]);
    }
}

// =====================================================================
// kernelB: partialX[ks] = inputs[m0:m0+32, kchunk] @ G[kchunk, n0:n0+128]
// fp16 3-term; inputs loaded fp32 and split in-kernel (no kPrepIn).
// grid (16 m, 2 n, 8 ksplit) = 256 CTAs, kchunk 512, 16 stages
// Per warp: M16 x N32 (8 warps as 2m x 4n).
// =====================================================================
#define KB_NST 16

__global__ __launch_bounds__(256, 2) void kernelB(const float* __restrict__ inputs)
{
    extern __shared__ __align__(16) char smem[];
    const uint32_t sb = smem_u32(smem);
    const int tid = threadIdx.x, wid = tid >> 5, lane = tid & 31;
    const int g = lane >> 2, tig = lane & 3;
    const int m0 = blockIdx.x * 32, n0 = blockIdx.y * 128;
    const int kbase = blockIdx.z * 512;

    const int arow = tid >> 3;
    const int aq   = tid & 7;

    float acc[4][4];
#pragma unroll
    for (int b = 0; b < 4; b++)
#pragma unroll
        for (int c = 0; c < 4; c++) acc[b][c] = 0.f;

    float4 ra;

    auto issueB = [&](int t, int b){
#pragma unroll
        for (int j = 0; j < 2; j++){
            int f = j*256 + tid, row = f >> 2, c = f & 3;
            uint32_t daddr = sb + b*B_BUFST + row*ROWB + c*16;
            size_t go = (size_t)(n0 + row) * NN + kbase + t*32 + c*8;
            cpasync16(daddr + B_OFF_BHI, g_Gt_hi + go);
            cpasync16(daddr + B_OFF_BLO, g_Gt_lo + go);
        }
        CP_COMMIT;
    };
    auto loadA = [&](int t){
        ra = __ldg((const float4*)(inputs + (size_t)(m0 + arow) * NN + kbase + t*32 + aq*4));
    };
    auto storeA = [&](int b){
        char* base = smem + b*B_BUFST;
        uint32_t h0, l0, h1, l1;
        split2h(ra.x, ra.y, h0, l0);
        split2h(ra.z, ra.w, h1, l1);
        *(uint2*)(base + B_OFF_AHI + arow*ROWB + aq*8) = make_uint2(h0, h1);
        *(uint2*)(base + B_OFF_ALO + arow*ROWB + aq*8) = make_uint2(l0, l1);
    };

    issueB(0, 0);
    loadA(0); storeA(0);
    CP_WAIT0; __syncthreads();

    const int am = (wid & 1) * 16 + g;
    const int bn = (wid >> 1) * 32 + g;

    for (int t = 0; t < KB_NST; t++){
        const int b = t & 1;
        if (t + 1 < KB_NST){ issueB(t + 1, b ^ 1); loadA(t + 1); }

        const char* buf = smem + b*B_BUFST;
#pragma unroll
        for (int s = 0; s < 2; s++){
            const int ko = s * 32 + tig * 4;
            const char* pa = buf + B_OFF_AHI + am * ROWB + ko;
            uint32_t ah[4] = { *(const uint32_t*)pa,        *(const uint32_t*)(pa + 8*ROWB),
                               *(const uint32_t*)(pa + 16), *(const uint32_t*)(pa + 8*ROWB + 16) };
            const char* ql = buf + B_OFF_ALO + am * ROWB + ko;
            uint32_t al[4] = { *(const uint32_t*)ql,        *(const uint32_t*)(ql + 8*ROWB),
                               *(const uint32_t*)(ql + 16), *(const uint32_t*)(ql + 8*ROWB + 16) };
#pragma unroll
            for (int ni = 0; ni < 4; ni++){
                const char* pb = buf + B_OFF_BHI + (bn + ni*8) * ROWB + ko;
                uint32_t bh[2] = { *(const uint32_t*)pb, *(const uint32_t*)(pb + 16) };
                const char* qb = buf + B_OFF_BLO + (bn + ni*8) * ROWB + ko;
                uint32_t bl[2] = { *(const uint32_t*)qb, *(const uint32_t*)(qb + 16) };
                mma16816h(acc[ni], ah, bh);
                mma16816h(acc[ni], ah, bl);
                mma16816h(acc[ni], al, bh);
            }
        }

        if (t + 1 < KB_NST) storeA(b ^ 1);
        CP_WAIT0; __syncthreads();
    }

    float* dst = g_partialX + (size_t)blockIdx.z * (BT * UN);
    const int m = m0 + am;
#pragma unroll
    for (int ni = 0; ni < 4; ni++){
        int n = n0 + bn - g + ni*8 + tig*2;
        *(float2*)(dst + (size_t)m * UN + n)       = make_float2(acc[ni][0], acc[ni][1]);
        *(float2*)(dst + (size_t)(m + 8) * UN + n) = make_float2(acc[ni][2], acc[ni][3]);
    }
}

// =====================================================================
// kReduceX: X = relu(sum of 8 partials)
// =====================================================================
__global__ void kReduceX()
{
    int i = blockIdx.x * blockDim.x + threadIdx.x;   // 32768 float4s
    const float4* p = (const float4*)g_partialX;
    float4 s = p[i];
#pragma unroll
    for (int s8 = 1; s8 < 8; s8++){
        float4 t = p[(size_t)s8 * (BT*UN/4) + i];
        s.x += t.x; s.y += t.y; s.z += t.z; s.w += t.w;
    }
    s.x = fmaxf(s.x, 0.f); s.y = fmaxf(s.y, 0.f);
    s.z = fmaxf(s.z, 0.f); s.w = fmaxf(s.w, 0.f);
    ((float4*)g_X)[i] = s;
}

// =====================================================================
// kernelC: GRU gates (fp32 CUDA cores)
// =====================================================================
__global__ __launch_bounds__(128, 4) void kernelC(const float* __restrict__ state,
    const float* __restrict__ wz, const float* __restrict__ uz, const float* __restrict__ bz,
    const float* __restrict__ wh, const float* __restrict__ uh, const float* __restrict__ bh,
    float* __restrict__ out)
{
    __shared__ float Xs[32][33];
    __shared__ float Ss[32][33];
    __shared__ float Wz[32][32], Uz[32][32], Wh[32][32], Uh[32][32];

    const int tid = threadIdx.x;
    const int tx = tid & 7;
    const int ty = tid >> 3;
    const int m0 = blockIdx.x * 32;
    const int n0 = blockIdx.y * 32;

    ull accz[2][2], acch[2][2];
#pragma unroll
    for (int i = 0; i < 2; i++)
#pragma unroll
        for (int j = 0; j < 2; j++){ accz[i][j] = 0ULL; acch[i][j] = 0ULL; }

    for (int kt = 0; kt < UN / 32; kt++){
        const int k0 = kt * 32;
        float4 xv[2], sv[2], wzv[2], uzv[2], whv[2], uhv[2];
#pragma unroll
        for (int u = 0; u < 2; u++){
            int f = tid + 128*u;
            int row = f >> 3; int c4 = (f & 7) * 4;
            xv[u]  = *(const float4*)(g_X  + (size_t)(m0 + row) * UN + k0 + c4);
            sv[u]  = *(const float4*)(state + (size_t)(m0 + row) * UN + k0 + c4);
            wzv[u] = *(const float4*)(wz + (size_t)(k0 + row) * UN + n0 + c4);
            uzv[u] = *(const float4*)(uz + (size_t)(k0 + row) * UN + n0 + c4);
            whv[u] = *(const float4*)(wh + (size_t)(k0 + row) * UN + n0 + c4);
            uhv[u] = *(const float4*)(uh + (size_t)(k0 + row) * UN + n0 + c4);
        }
        __syncthreads();
#pragma unroll
        for (int u = 0; u < 2; u++){
            int f = tid + 128*u;
            int row = f >> 3; int c4 = (f & 7) * 4;
            Xs[c4+0][row] = xv[u].x; Xs[c4+1][row] = xv[u].y;
            Xs[c4+2][row] = xv[u].z; Xs[c4+3][row] = xv[u].w;
            Ss[c4+0][row] = sv[u].x; Ss[c4+1][row] = sv[u].y;
            Ss[c4+2][row] = sv[u].z; Ss[c4+3][row] = sv[u].w;
            *(float4*)&Wz[row][c4] = wzv[u];
            *(float4*)&Uz[row][c4] = uzv[u];
            *(float4*)&Wh[row][c4] = whv[u];
            *(float4*)&Uh[row][c4] = uhv[u];
        }
        __syncthreads();

#pragma unroll 8
        for (int kk = 0; kk < 32; kk++){
            float x0 = Xs[kk][ty*2], x1 = Xs[kk][ty*2+1];
            float s0 = Ss[kk][ty*2], s1 = Ss[kk][ty*2+1];
            ull xx0 = pack2(x0, x0), xx1 = pack2(x1, x1);
            ull ss0 = pack2(s0, s0), ss1 = pack2(s1, s1);
            const ull* wzp = (const ull*)&Wz[kk][tx*4];
            const ull* uzp = (const ull*)&Uz[kk][tx*4];
            const ull* whp = (const ull*)&Wh[kk][tx*4];
            const ull* uhp = (const ull*)&Uh[kk][tx*4];
            ull wz0 = wzp[0], wz1 = wzp[1], uz0 = uzp[0], uz1 = uzp[1];
            ull wh0 = whp[0], wh1 = whp[1], uh0 = uhp[0], uh1 = uhp[1];
            fma2(accz[0][0], xx0, wz0); fma2(accz[0][1], xx0, wz1);
            fma2(accz[1][0], xx1, wz0); fma2(accz[1][1], xx1, wz1);
            fma2(accz[0][0], ss0, uz0); fma2(accz[0][1], ss0, uz1);
            fma2(accz[1][0], ss1, uz0); fma2(accz[1][1], ss1, uz1);
            fma2(acch[0][0], xx0, wh0); fma2(acch[0][1], xx0, wh1);
            fma2(acch[1][0], xx1, wh0); fma2(acch[1][1], xx1, wh1);
            fma2(acch[0][0], ss0, uh0); fma2(acch[0][1], ss0, uh1);
            fma2(acch[1][0], ss1, uh0); fma2(acch[1][1], ss1, uh1);
        }
    }

#pragma unroll
    for (int i = 0; i < 2; i++){
        int row = m0 + ty*2 + i;
#pragma unroll
        for (int jp = 0; jp < 2; jp++){
            float2 vz = unpack2(accz[i][jp]);
            float2 vh = unpack2(acch[i][jp]);
            int c = n0 + tx*4 + jp*2;
#pragma unroll
            for (int w = 0; w < 2; w++){
                float pz = (w ? vz.y : vz.x) + bz[c + w];
                float ph = (w ? vh.y : vh.x) + bh[c + w];
                float z = 1.0f / (1.0f + expf(-pz));
                float h = tanhf(ph);
                float st = state[(size_t)row * UN + c + w];
                out[(size_t)row * UN + c + w] = st + z * (h - st);
            }
        }
    }
}

// =====================================================================
extern "C" void kernel_launch(void* const* d_in, const int* in_sizes, int n_in,
                              void* d_out, int out_size)
{
    const float* inputs = (const float*)d_in[0];
    const float* state  = (const float*)d_in[1];
    const float* adj    = (const float*)d_in[2];
    const float* wa     = (const float*)d_in[3];
    const float* wgcn   = (const float*)d_in[4];
    const float* wz     = (const float*)d_in[5];
    const float* uz     = (const float*)d_in[6];
    const float* bz     = (const float*)d_in[7];
    const float* wh     = (const float*)d_in[8];
    const float* uh     = (const float*)d_in[9];
    const float* bh     = (const float*)d_in[10];
    float* out = (float*)d_out;

    cudaFuncSetAttribute(kernelA, cudaFuncAttributeMaxDynamicSharedMemorySize, A_SMEMSZ);
    cudaFuncSetAttribute(kernelB, cudaFuncAttributeMaxDynamicSharedMemorySize, B_SMEMSZ);

    kPrepW<<<dim3(NN/32, UN/32), 256>>>(wgcn);
    kernelA<<<dim3(128, 4), 256, A_SMEMSZ>>>(adj, wa);
    kReduceGT<<<dim3(NN/32, UN/32), 256>>>();
    kernelB<<<dim3(16, 2, 8), 256, B_SMEMSZ>>>(inputs);
    kReduceX<<<128, 256>>>();
    kernelC<<<dim3(16, 8), 128>>>(state, wz, uz, bz, wh, uh, bh, out);
}

// round 9
// speedup vs baseline: 1.0361x; 1.0361x over previous
#include <cuda_runtime.h>
#include <math.h>
#include <stdint.h>

typedef unsigned long long ull;
typedef unsigned short u16;

#define NN 4096
#define UN 256
#define BT 512

// ================= helpers =================
__device__ __forceinline__ uint32_t smem_u32(const void* p){
    uint32_t a;
    asm("{ .reg .u64 t; cvta.to.shared.u64 t, %1; cvt.u32.u64 %0, t; }" : "=r"(a) : "l"(p));
    return a;
}
__device__ __forceinline__ void cpasync16(uint32_t daddr, const void* gptr){
    asm volatile("cp.async.cg.shared.global [%0], [%1], 16;" :: "r"(daddr), "l"(gptr));
}
#define CP_COMMIT asm volatile("cp.async.commit_group;" ::: "memory")
#define CP_WAIT0  asm volatile("cp.async.wait_group 0;" ::: "memory")

// fp16 hi/lo split helpers
__device__ __forceinline__ void split2h(float v0, float v1, uint32_t& hp, uint32_t& lp){
    u16 h0, h1, l0, l1;
    asm("cvt.rn.f16.f32 %0, %1;" : "=h"(h0) : "f"(v0));
    asm("cvt.rn.f16.f32 %0, %1;" : "=h"(h1) : "f"(v1));
    float f0, f1;
    asm("cvt.f32.f16 %0, %1;" : "=f"(f0) : "h"(h0));
    asm("cvt.f32.f16 %0, %1;" : "=f"(f1) : "h"(h1));
    asm("cvt.rn.f16.f32 %0, %1;" : "=h"(l0) : "f"(v0 - f0));
    asm("cvt.rn.f16.f32 %0, %1;" : "=h"(l1) : "f"(v1 - f1));
    asm("mov.b32 %0, {%1, %2};" : "=r"(hp) : "h"(h0), "h"(h1));
    asm("mov.b32 %0, {%1, %2};" : "=r"(lp) : "h"(l0), "h"(l1));
}
__device__ __forceinline__ void split1h(float v, u16& h, u16& l){
    u16 hb, lb;
    asm("cvt.rn.f16.f32 %0, %1;" : "=h"(hb) : "f"(v));
    float hf;
    asm("cvt.f32.f16 %0, %1;" : "=f"(hf) : "h"(hb));
    asm("cvt.rn.f16.f32 %0, %1;" : "=h"(lb) : "f"(v - hf));
    h = hb; l = lb;
}
__device__ __forceinline__ u16 cvt1h(float v){
    u16 hb;
    asm("cvt.rn.f16.f32 %0, %1;" : "=h"(hb) : "f"(v));
    return hb;
}

__device__ __forceinline__ void mma16816h(float* d, const uint32_t* a, const uint32_t* b){
    asm volatile("mma.sync.aligned.m16n8k16.row.col.f32.f16.f16.f32 "
        "{%0,%1,%2,%3}, {%4,%5,%6,%7}, {%8,%9}, {%0,%1,%2,%3};"
        : "+f"(d[0]), "+f"(d[1]), "+f"(d[2]), "+f"(d[3])
        : "r"(a[0]), "r"(a[1]), "r"(a[2]), "r"(a[3]), "r"(b[0]), "r"(b[1]));
}

// ================= static device scratch =================
__device__ __align__(16) float g_partialG[4u * NN * UN];   // 16 MB
__device__ __align__(16) u16   g_wth[UN * NN];             // 2 MB  w_gcn^T fp16
__device__ __align__(16) u16   g_Gt_hi[UN * NN];           // 2 MB  G^T fp16 hi
__device__ __align__(16) u16   g_Gt_lo[UN * NN];           // 2 MB
__device__ __align__(16) float g_partialX[8u * BT * UN];   // 4 MB
__device__ __align__(16) float g_X[BT * UN];               // 0.5 MB
// Gate weights: Bt[n'][k'], n' in [0,512): n'<256 => z-gate col n', n'>=256 => h-gate col n'-256
// k' in [0,512): k'<256 => W (multiplies X), k'>=256 => U (multiplies state)
__device__ __align__(16) u16   g_gw_hi[512 * 512];         // 512 KB
__device__ __align__(16) u16   g_gw_lo[512 * 512];         // 512 KB

// ================= SMEM geometry =================
#define ROWB 80
// kernelA: [A_hi 2560][A_lo 2560][B 20480]  (M=32, N=256, BK=32)
#define A_OFF_AHI 0
#define A_OFF_ALO 2560
#define A_OFF_B   5120
#define A_BUFST   25600
#define A_SMEMSZ  (2 * A_BUFST)
// kernelB: M=64, N=128, BK=32: [A_hi 5120][A_lo 5120][B_hi 10240][B_lo 10240]
#define B_OFF_AHI 0
#define B_OFF_ALO 5120
#define B_OFF_BHI 10240
#define B_OFF_BLO 20480
#define B_BUFST   30720
#define B_SMEMSZ  (2 * B_BUFST)
// kernelC: M=32, N=128(64 z + 64 h), BK=32: [A_hi 2560][A_lo 2560][B_hi 10240][B_lo 10240]
#define C_OFF_AHI 0
#define C_OFF_ALO 2560
#define C_OFF_BHI 5120
#define C_OFF_BLO 15360
#define C_BUFST   25600
#define C_SMEMSZ  (2 * C_BUFST)

// =====================================================================
// kPrepW: w_gcn [4096][256] -> g_wth [256][4096] fp16 (transpose)
// =====================================================================
__global__ void kPrepW(const float* __restrict__ wgcn)
{
    __shared__ float tile[32][33];
    const int k0 = blockIdx.x * 32, n0 = blockIdx.y * 32;
    const int c = threadIdx.x & 31, r = threadIdx.x >> 5;
#pragma unroll
    for (int i = 0; i < 4; i++)
        tile[r + 8*i][c] = wgcn[(size_t)(k0 + r + 8*i) * UN + n0 + c];
    __syncthreads();
#pragma unroll
    for (int i = 0; i < 4; i++){
        size_t o = (size_t)(n0 + r + 8*i) * NN + k0 + c;
        g_wth[o] = cvt1h(tile[c][r + 8*i]);
    }
}

// =====================================================================
// kPrepGates: wz/uz/wh/uh [256][256] -> g_gw_hi/lo [512 n'][512 k'] (transpose+split)
// grid (16 k'-tiles, 16 n'-tiles)
// =====================================================================
__global__ void kPrepGates(const float* __restrict__ wz, const float* __restrict__ uz,
                           const float* __restrict__ wh, const float* __restrict__ uh)
{
    __shared__ float tile[32][33];
    const int k0 = blockIdx.x * 32, n0 = blockIdx.y * 32;
    const int c = threadIdx.x & 31, r = threadIdx.x >> 5;
#pragma unroll
    for (int i = 0; i < 4; i++){
        int kk = k0 + r + 8*i;       // k'
        int nn = n0 + c;             // n'
        const float* src = (kk < 256) ? ((nn < 256) ? wz : wh) : ((nn < 256) ? uz : uh);
        tile[r + 8*i][c] = src[(size_t)(kk & 255) * UN + (nn & 255)];
    }
    __syncthreads();
#pragma unroll
    for (int i = 0; i < 4; i++){
        float v = tile[c][r + 8*i];
        size_t o = (size_t)(n0 + r + 8*i) * 512 + k0 + c;
        split1h(v, g_gw_hi[o], g_gw_lo[o]);
    }
}

// =====================================================================
// kernelA: partialG[ks] = adj_mix[m0:m0+32, ks*1024:+1024] @ w_gcn  (fp16 2-term)
// grid (128 m-tiles, 4 ksplit) = 512 CTAs, 256 threads, occ 2
// =====================================================================
#define KA_NST 32

__global__ __launch_bounds__(256, 2) void kernelA(const float* __restrict__ adj,
                                                  const float* __restrict__ wap)
{
    extern __shared__ __align__(16) char smem[];
    const uint32_t sb = smem_u32(smem);
    const int tid = threadIdx.x, wid = tid >> 5, lane = tid & 31;
    const int g = lane >> 2, tig = lane & 3;
    const int m0 = blockIdx.x * 32;
    const int kbase = blockIdx.y * 1024;
    const float w0 = wap[0], w1 = wap[1], w2 = wap[2];
    const size_t GS = (size_t)NN * NN;

    const int arow = tid >> 3;
    const int aq   = tid & 7;

    float acc[8][4];
#pragma unroll
    for (int b = 0; b < 8; b++)
#pragma unroll
        for (int c = 0; c < 4; c++) acc[b][c] = 0.f;

    float4 ra[3];

    auto issueB = [&](int t, int b){
#pragma unroll
        for (int j = 0; j < 4; j++){
            int f = j*256 + tid, row = f >> 2, c = f & 3;
            uint32_t daddr = sb + b*A_BUFST + A_OFF_B + row*ROWB + c*16;
            size_t go = (size_t)row * NN + kbase + t*32 + c*8;
            cpasync16(daddr, g_wth + go);
        }
        CP_COMMIT;
    };
    auto loadA = [&](int t){
        const float* p = adj + (size_t)(m0 + arow) * NN + kbase + t*32 + aq*4;
        ra[0] = __ldg((const float4*)p);
        ra[1] = __ldg((const float4*)(p + GS));
        ra[2] = __ldg((const float4*)(p + 2*GS));
    };
    auto storeA = [&](int b){
        char* base = smem + b*A_BUFST;
        float vx = fmaf(w0, ra[0].x, fmaf(w1, ra[1].x, w2*ra[2].x));
        float vy = fmaf(w0, ra[0].y, fmaf(w1, ra[1].y, w2*ra[2].y));
        float vz = fmaf(w0, ra[0].z, fmaf(w1, ra[1].z, w2*ra[2].z));
        float vw = fmaf(w0, ra[0].w, fmaf(w1, ra[1].w, w2*ra[2].w));
        uint32_t h0, l0, h1, l1;
        split2h(vx, vy, h0, l0);
        split2h(vz, vw, h1, l1);
        *(uint2*)(base + A_OFF_AHI + arow*ROWB + aq*8) = make_uint2(h0, h1);
        *(uint2*)(base + A_OFF_ALO + arow*ROWB + aq*8) = make_uint2(l0, l1);
    };

    issueB(0, 0);
    loadA(0); storeA(0);
    CP_WAIT0; __syncthreads();

    const int am = (wid & 1) * 16 + g;
    const int bn = (wid >> 1) * 64 + g;

    for (int t = 0; t < KA_NST; t++){
        const int b = t & 1;
        if (t + 1 < KA_NST){ issueB(t + 1, b ^ 1); loadA(t + 1); }

        const char* buf = smem + b*A_BUFST;
#pragma unroll
        for (int s = 0; s < 2; s++){
            const int ko = s * 32 + tig * 4;
            const char* pa = buf + A_OFF_AHI + am * ROWB + ko;
            uint32_t ah[4] = { *(const uint32_t*)pa,        *(const uint32_t*)(pa + 8*ROWB),
                               *(const uint32_t*)(pa + 16), *(const uint32_t*)(pa + 8*ROWB + 16) };
            const char* ql = buf + A_OFF_ALO + am * ROWB + ko;
            uint32_t al[4] = { *(const uint32_t*)ql,        *(const uint32_t*)(ql + 8*ROWB),
                               *(const uint32_t*)(ql + 16), *(const uint32_t*)(ql + 8*ROWB + 16) };
#pragma unroll
            for (int ni = 0; ni < 8; ni++){
                const char* pb = buf + A_OFF_B + (bn + ni*8) * ROWB + ko;
                uint32_t bh[2] = { *(const uint32_t*)pb, *(const uint32_t*)(pb + 16) };
                mma16816h(acc[ni], ah, bh);
                mma16816h(acc[ni], al, bh);
            }
        }

        if (t + 1 < KA_NST) storeA(b ^ 1);
        CP_WAIT0; __syncthreads();
    }

    float* dst = g_partialG + (size_t)blockIdx.y * (NN * UN);
    const int m = m0 + am;
#pragma unroll
    for (int ni = 0; ni < 8; ni++){
        int n = bn - g + ni*8 + tig*2;
        *(float2*)(dst + (size_t)m * UN + n)       = make_float2(acc[ni][0], acc[ni][1]);
        *(float2*)(dst + (size_t)(m + 8) * UN + n) = make_float2(acc[ni][2], acc[ni][3]);
    }
}

// =====================================================================
// kReduceGT: G = sum of 4 partials; transpose + fp16 split -> g_Gt_hi/lo
// =====================================================================
__global__ void kReduceGT()
{
    __shared__ float tile[32][33];
    const int k0 = blockIdx.x * 32, n0 = blockIdx.y * 32;
    const int c = threadIdx.x & 31, r = threadIdx.x >> 5;
#pragma unroll
    for (int i = 0; i < 4; i++){
        size_t o = (size_t)(k0 + r + 8*i) * UN + n0 + c;
        float s = g_partialG[o];
#pragma unroll
        for (int p = 1; p < 4; p++) s += g_partialG[(size_t)p * NN * UN + o];
        tile[r + 8*i][c] = s;
    }
    __syncthreads();
#pragma unroll
    for (int i = 0; i < 4; i++){
        float v = tile[c][r + 8*i];
        size_t o = (size_t)(n0 + r + 8*i) * NN + k0 + c;
        split1h(v, g_Gt_hi[o], g_Gt_lo[o]);
    }
}

// =====================================================================
// kernelB: partialX[ks] = inputs[m0:m0+64, kchunk] @ G[kchunk, n0:n0+128]
// fp16 3-term; grid (8 m, 2 n, 8 ksplit) = 128 CTAs, kchunk 512, 16 stages
// =====================================================================
#define KB_NST 16

__global__ __launch_bounds__(256, 2) void kernelB(const float* __restrict__ inputs)
{
    extern __shared__ __align__(16) char smem[];
    const uint32_t sb = smem_u32(smem);
    const int tid = threadIdx.x, wid = tid >> 5, lane = tid & 31;
    const int g = lane >> 2, tig = lane & 3;
    const int m0 = blockIdx.x * 64, n0 = blockIdx.y * 128;
    const int kbase = blockIdx.z * 512;

    float acc[2][4][4];
#pragma unroll
    for (int a = 0; a < 2; a++)
#pragma unroll
        for (int b = 0; b < 4; b++)
#pragma unroll
            for (int c = 0; c < 4; c++) acc[a][b][c] = 0.f;

    float4 ra[2];

    auto issueB = [&](int t, int b){
#pragma unroll
        for (int j = 0; j < 2; j++){
            int f = j*256 + tid, row = f >> 2, c = f & 3;
            uint32_t daddr = sb + b*B_BUFST + row*ROWB + c*16;
            size_t go = (size_t)(n0 + row) * NN + kbase + t*32 + c*8;
            cpasync16(daddr + B_OFF_BHI, g_Gt_hi + go);
            cpasync16(daddr + B_OFF_BLO, g_Gt_lo + go);
        }
        CP_COMMIT;
    };
    auto loadA = [&](int t){
#pragma unroll
        for (int j = 0; j < 2; j++){
            int f = j*256 + tid, row = f >> 3, q = f & 7;
            ra[j] = __ldg((const float4*)(inputs + (size_t)(m0 + row) * NN + kbase + t*32 + q*4));
        }
    };
    auto storeA = [&](int b){
        char* base = smem + b*B_BUFST;
#pragma unroll
        for (int j = 0; j < 2; j++){
            int f = j*256 + tid, row = f >> 3, q = f & 7;
            uint32_t h0, l0, h1, l1;
            split2h(ra[j].x, ra[j].y, h0, l0);
            split2h(ra[j].z, ra[j].w, h1, l1);
            *(uint2*)(base + B_OFF_AHI + row*ROWB + q*8) = make_uint2(h0, h1);
            *(uint2*)(base + B_OFF_ALO + row*ROWB + q*8) = make_uint2(l0, l1);
        }
    };

    issueB(0, 0);
    loadA(0); storeA(0);
    CP_WAIT0; __syncthreads();

    const int am = (wid & 1) * 32 + g;
    const int bn = (wid >> 1) * 32 + g;

    for (int t = 0; t < KB_NST; t++){
        const int b = t & 1;
        if (t + 1 < KB_NST){ issueB(t + 1, b ^ 1); loadA(t + 1); }

        const char* buf = smem + b*B_BUFST;
#pragma unroll
        for (int s = 0; s < 2; s++){
            const int ko = s * 32 + tig * 4;
            uint32_t ah[2][4], al[2][4];
#pragma unroll
            for (int mi = 0; mi < 2; mi++){
                const char* pa = buf + B_OFF_AHI + (am + mi*16) * ROWB + ko;
                ah[mi][0] = *(const uint32_t*)pa;        ah[mi][1] = *(const uint32_t*)(pa + 8*ROWB);
                ah[mi][2] = *(const uint32_t*)(pa + 16); ah[mi][3] = *(const uint32_t*)(pa + 8*ROWB + 16);
                const char* ql = buf + B_OFF_ALO + (am + mi*16) * ROWB + ko;
                al[mi][0] = *(const uint32_t*)ql;        al[mi][1] = *(const uint32_t*)(ql + 8*ROWB);
                al[mi][2] = *(const uint32_t*)(ql + 16); al[mi][3] = *(const uint32_t*)(ql + 8*ROWB + 16);
            }
#pragma unroll
            for (int ni = 0; ni < 4; ni++){
                const char* pb = buf + B_OFF_BHI + (bn + ni*8) * ROWB + ko;
                uint32_t bh[2] = { *(const uint32_t*)pb, *(const uint32_t*)(pb + 16) };
                const char* qb = buf + B_OFF_BLO + (bn + ni*8) * ROWB + ko;
                uint32_t bl[2] = { *(const uint32_t*)qb, *(const uint32_t*)(qb + 16) };
#pragma unroll
                for (int mi = 0; mi < 2; mi++){
                    mma16816h(acc[mi][ni], ah[mi], bh);
                    mma16816h(acc[mi][ni], ah[mi], bl);
                    mma16816h(acc[mi][ni], al[mi], bh);
                }
            }
        }

        if (t + 1 < KB_NST) storeA(b ^ 1);
        CP_WAIT0; __syncthreads();
    }

    float* dst = g_partialX + (size_t)blockIdx.z * (BT * UN);
#pragma unroll
    for (int mi = 0; mi < 2; mi++){
        int m = m0 + am + mi*16;
#pragma unroll
        for (int ni = 0; ni < 4; ni++){
            int n = n0 + bn - g + ni*8 + tig*2;
            *(float2*)(dst + (size_t)m * UN + n)       = make_float2(acc[mi][ni][0], acc[mi][ni][1]);
            *(float2*)(dst + (size_t)(m + 8) * UN + n) = make_float2(acc[mi][ni][2], acc[mi][ni][3]);
        }
    }
}

// =====================================================================
// kReduceX: X = relu(sum of 8 partials)
// =====================================================================
__global__ void kReduceX()
{
    int i = blockIdx.x * blockDim.x + threadIdx.x;   // 32768 float4s
    const float4* p = (const float4*)g_partialX;
    float4 s = p[i];
#pragma unroll
    for (int s8 = 1; s8 < 8; s8++){
        float4 t = p[(size_t)s8 * (BT*UN/4) + i];
        s.x += t.x; s.y += t.y; s.z += t.z; s.w += t.w;
    }
    s.x = fmaxf(s.x, 0.f); s.y = fmaxf(s.y, 0.f);
    s.z = fmaxf(s.z, 0.f); s.w = fmaxf(s.w, 0.f);
    ((float4*)g_X)[i] = s;
}

// =====================================================================
// kernelC: GRU gates via one fused 512x512x512 fp16 3-term GEMM + gate epilogue
// A = [X | state] (split in-kernel), B = g_gw (pre-split).
// grid (16 m-tiles, 4 n-tiles) = 64 CTAs. Per CTA: M=32, N=64 z-cols + 64 h-cols.
// =====================================================================
#define KC_NST 16

__global__ __launch_bounds__(256, 2) void kernelC(const float* __restrict__ state,
    const float* __restrict__ bz, const float* __restrict__ bh,
    float* __restrict__ out)
{
    extern __shared__ __align__(16) char smem[];
    const uint32_t sb = smem_u32(smem);
    const int tid = threadIdx.x, wid = tid >> 5, lane = tid & 31;
    const int g = lane >> 2, tig = lane & 3;
    const int m0 = blockIdx.x * 32;
    const int n0 = blockIdx.y * 64;

    float accz[2][4], acch[2][4];
#pragma unroll
    for (int a = 0; a < 2; a++)
#pragma unroll
        for (int c = 0; c < 4; c++){ accz[a][c] = 0.f; acch[a][c] = 0.f; }

    const int arow = tid >> 3;
    const int aq   = tid & 7;
    float4 ra;

    auto issueB = [&](int t, int b){
#pragma unroll
        for (int j = 0; j < 2; j++){
            int f = j*256 + tid, r = f >> 2, c = f & 3;
            int nprime = (r < 64) ? (n0 + r) : (256 + n0 + (r - 64));
            uint32_t daddr = sb + b*C_BUFST + r*ROWB + c*16;
            size_t go = (size_t)nprime * 512 + t*32 + c*8;
            cpasync16(daddr + C_OFF_BHI, g_gw_hi + go);
            cpasync16(daddr + C_OFF_BLO, g_gw_lo + go);
        }
        CP_COMMIT;
    };
    auto loadA = [&](int t){
        int kp = t*32 + aq*4;
        if (kp < 256)
            ra = *(const float4*)(g_X + (size_t)(m0 + arow) * UN + kp);
        else
            ra = __ldg((const float4*)(state + (size_t)(m0 + arow) * UN + (kp - 256)));
    };
    auto storeA = [&](int b){
        char* base = smem + b*C_BUFST;
        uint32_t h0, l0, h1, l1;
        split2h(ra.x, ra.y, h0, l0);
        split2h(ra.z, ra.w, h1, l1);
        *(uint2*)(base + C_OFF_AHI + arow*ROWB + aq*8) = make_uint2(h0, h1);
        *(uint2*)(base + C_OFF_ALO + arow*ROWB + aq*8) = make_uint2(l0, l1);
    };

    issueB(0, 0);
    loadA(0); storeA(0);
    CP_WAIT0; __syncthreads();

    const int am = (wid & 1) * 16 + g;
    const int bn = (wid >> 1) * 16;

    for (int t = 0; t < KC_NST; t++){
        const int b = t & 1;
        if (t + 1 < KC_NST){ issueB(t + 1, b ^ 1); loadA(t + 1); }

        const char* buf = smem + b*C_BUFST;
#pragma unroll
        for (int s = 0; s < 2; s++){
            const int ko = s * 32 + tig * 4;
            const char* pa = buf + C_OFF_AHI + am * ROWB + ko;
            uint32_t ah[4] = { *(const uint32_t*)pa,        *(const uint32_t*)(pa + 8*ROWB),
                               *(const uint32_t*)(pa + 16), *(const uint32_t*)(pa + 8*ROWB + 16) };
            const char* ql = buf + C_OFF_ALO + am * ROWB + ko;
            uint32_t al[4] = { *(const uint32_t*)ql,        *(const uint32_t*)(ql + 8*ROWB),
                               *(const uint32_t*)(ql + 16), *(const uint32_t*)(ql + 8*ROWB + 16) };
#pragma unroll
            for (int ni = 0; ni < 2; ni++){
                const char* pb = buf + C_OFF_BHI + (bn + g + ni*8) * ROWB + ko;
                uint32_t bhz[2] = { *(const uint32_t*)pb, *(const uint32_t*)(pb + 16) };
                const char* qb = buf + C_OFF_BLO + (bn + g + ni*8) * ROWB + ko;
                uint32_t blz[2] = { *(const uint32_t*)qb, *(const uint32_t*)(qb + 16) };
                mma16816h(accz[ni], ah, bhz);
                mma16816h(accz[ni], ah, blz);
                mma16816h(accz[ni], al, bhz);
                const char* ph = buf + C_OFF_BHI + (64 + bn + g + ni*8) * ROWB + ko;
                uint32_t bhh[2] = { *(const uint32_t*)ph, *(const uint32_t*)(ph + 16) };
                const char* qh = buf + C_OFF_BLO + (64 + bn + g + ni*8) * ROWB + ko;
                uint32_t blh[2] = { *(const uint32_t*)qh, *(const uint32_t*)(qh + 16) };
                mma16816h(acch[ni], ah, bhh);
                mma16816h(acch[ni], ah, blh);
                mma16816h(acch[ni], al, bhh);
            }
        }

        if (t + 1 < KC_NST) storeA(b ^ 1);
        CP_WAIT0; __syncthreads();
    }

    // ---- gate epilogue ----
#pragma unroll
    for (int ni = 0; ni < 2; ni++){
        int n = n0 + bn + ni*8 + tig*2;
        float2 bzv = *(const float2*)(bz + n);
        float2 bhv = *(const float2*)(bh + n);
#pragma unroll
        for (int half = 0; half < 2; half++){
            int m = m0 + am + half*8;
            float pz0 = accz[ni][half*2+0] + bzv.x;
            float pz1 = accz[ni][half*2+1] + bzv.y;
            float ph0 = acch[ni][half*2+0] + bhv.x;
            float ph1 = acch[ni][half*2+1] + bhv.y;
            float2 sv = *(const float2*)(state + (size_t)m * UN + n);
            float z0 = 1.0f / (1.0f + expf(-pz0));
            float z1 = 1.0f / (1.0f + expf(-pz1));
            float h0 = tanhf(ph0);
            float h1 = tanhf(ph1);
            float o0 = sv.x + z0 * (h0 - sv.x);
            float o1 = sv.y + z1 * (h1 - sv.y);
            *(float2*)(out + (size_t)m * UN + n) = make_float2(o0, o1);
        }
    }
}

// =====================================================================
extern "C" void kernel_launch(void* const* d_in, const int* in_sizes, int n_in,
                              void* d_out, int out_size)
{
    const float* inputs = (const float*)d_in[0];
    const float* state  = (const float*)d_in[1];
    const float* adj    = (const float*)d_in[2];
    const float* wa     = (const float*)d_in[3];
    const float* wgcn   = (const float*)d_in[4];
    const float* wz     = (const float*)d_in[5];
    const float* uz     = (const float*)d_in[6];
    const float* bz     = (const float*)d_in[7];
    const float* wh     = (const float*)d_in[8];
    const float* uh     = (const float*)d_in[9];
    const float* bh     = (const float*)d_in[10];
    float* out = (float*)d_out;

    cudaFuncSetAttribute(kernelA, cudaFuncAttributeMaxDynamicSharedMemorySize, A_SMEMSZ);
    cudaFuncSetAttribute(kernelB, cudaFuncAttributeMaxDynamicSharedMemorySize, B_SMEMSZ);
    cudaFuncSetAttribute(kernelC, cudaFuncAttributeMaxDynamicSharedMemorySize, C_SMEMSZ);

    kPrepW<<<dim3(NN/32, UN/32), 256>>>(wgcn);
    kPrepGates<<<dim3(16, 16), 256>>>(wz, uz, wh, uh);
    kernelA<<<dim3(128, 4), 256, A_SMEMSZ>>>(adj, wa);
    kReduceGT<<<dim3(NN/32, UN/32), 256>>>();
    kernelB<<<dim3(8, 2, 8), 256, B_SMEMSZ>>>(inputs);
    kReduceX<<<128, 256>>>();
    kernelC<<<dim3(16, 4), 256, C_SMEMSZ>>>(state, bz, bh, out);
}